// round 11
// baseline (speedup 1.0000x reference)
#include <cuda_runtime.h>
#include <math.h>

#define HW 65536
#define C_ 64
#define R_ 8
#define B_ 4
#define GRID 1024

// ---------------- device scratch (no allocations allowed) ----------------
__device__ int d_c1 = 0, d_c2 = 0, d_c3 = 0;             // grid-sync counters (self-resetting)
__device__ float d_partial[16][64];                      // [plane=(b*4+i)][chunk]
__device__ __align__(16) float d_kp4[B_][R_][C_][4];     // folded kernel @ W1
__device__ __align__(16) float d_kb4[B_][R_][C_];        // folded kernel @ b1
__device__ __align__(16) float d_wgp[R_][4];             // Wg @ W1
__device__ float d_bgp[R_];                              // Wg @ b1 + bg

__device__ __forceinline__ void gsync(int* ctr, int target) {
    __syncthreads();
    if (threadIdx.x == 0) {
        __threadfence();
        atomicAdd(ctr, 1);
        while (*(volatile int*)ctr < target) __nanosleep(64);
    }
    __syncthreads();
    __threadfence();
}

// ---------------- single persistent kernel: reduce -> gen -> stream ----------------
// 1024 blocks x 256 threads, all co-resident: launch_bounds(256,7) caps regs at 36,
// smem 17KB -> 7 blocks/SM x 148 = 1036 >= 1024.
__global__ void __launch_bounds__(256, 7) fused_kernel(
        const float* __restrict__ rgb, const float* __restrict__ edge,
        const float* __restrict__ W1, const float* __restrict__ b1,
        const float* __restrict__ Wk1, const float* __restrict__ bk1,
        const float* __restrict__ Wk2, const float* __restrict__ bk2,
        const float* __restrict__ Wg, const float* __restrict__ bg,
        float* __restrict__ out) {
    // shared union: phase2 uses kern[4096]+small; phase3 uses skp/skb4/sgw/sgb
    __shared__ __align__(16) char buf[17408];
    int tid = threadIdx.x, bid = blockIdx.x;

    // ---- phase 1: partial sums. plane = bid>>6 (16), chunk = bid&63 (64x1024 floats) ----
    {
        int plane = bid >> 6, chunk = bid & 63;
        int pb = plane >> 2, i = plane & 3;
        const float* src = (i < 3) ? (rgb + (size_t)(pb * 3 + i) * HW)
                                   : (edge + (size_t)pb * HW);
        float4 v = ((const float4*)src)[chunk * 256 + tid];
        float s = (v.x + v.y) + (v.z + v.w);
#pragma unroll
        for (int off = 16; off; off >>= 1) s += __shfl_down_sync(0xFFFFFFFFu, s, off);
        float* ws = (float*)buf;                         // 8 floats
        if ((tid & 31) == 0) ws[tid >> 5] = s;
        __syncthreads();
        if (tid == 0) {
            float t = ws[0];
#pragma unroll
            for (int w = 1; w < 8; w++) t += ws[w];
            d_partial[plane][chunk] = t;
        }
    }

    gsync(&d_c1, GRID);

    // ---- phase 2: blocks 0..31 generate folded kernels (others pass straight to sync2) ----
    if (bid < 32) {
        float* kern = (float*)buf;                       // 4096 floats
        float* m4 = (float*)(buf + 16384);               // 4
        float* g  = (float*)(buf + 16400);               // 64
        float* tg = (float*)(buf + 16656);               // 8
        int b = bid >> 3, r = bid & 7;

        if (tid < 4) {
            float s = 0.f;
#pragma unroll
            for (int ch = 0; ch < 64; ch++) s += d_partial[b * 4 + tid][ch];
            m4[tid] = s * (1.0f / 65536.0f);
        }
        __syncthreads();
        if (tid < 64) {
            g[tid] = b1[tid] + W1[tid * 4 + 0] * m4[0] + W1[tid * 4 + 1] * m4[1]
                             + W1[tid * 4 + 2] * m4[2] + W1[tid * 4 + 3] * m4[3];
        }
        __syncthreads();
        if (tid < 8) {
            int row = r * 8 + tid;
            float a = bk1[row];
#pragma unroll 8
            for (int c = 0; c < 64; c++) a += Wk1[row * 64 + c] * g[c];
            tg[tid] = 1.f / (1.f + expf(-a));
        }
        __syncthreads();

        const float4* w2 = (const float4*)(Wk2 + (size_t)r * 4096 * 8);
        const float* bk = bk2 + r * 4096;
        float t0 = tg[0], t1 = tg[1], t2 = tg[2], t3 = tg[3];
        float t4 = tg[4], t5 = tg[5], t6 = tg[6], t7 = tg[7];
#pragma unroll
        for (int it = 0; it < 16; it++) {
            int o = tid + it * 256;
            float4 wa = w2[o * 2], wb = w2[o * 2 + 1];
            kern[o] = bk[o] + t0 * wa.x + t1 * wa.y + t2 * wa.z + t3 * wa.w
                            + t4 * wb.x + t5 * wb.y + t6 * wb.z + t7 * wb.w;
        }
        __syncthreads();

        int c = tid >> 2, j = tid & 3;                   // 64 x 4 threads
        float acc = 0.f;
#pragma unroll 8
        for (int ci = 0; ci < 64; ci++) acc += kern[c * 64 + ci] * W1[ci * 4 + j];
        d_kp4[b][r][c][j] = acc;
        if (j == 0) {
            float ab = 0.f;
#pragma unroll 8
            for (int ci = 0; ci < 64; ci++) ab += kern[c * 64 + ci] * b1[ci];
            d_kb4[b][r][c] = ab;
        }
        if (bid == 0) {                                  // folded guide weights
            if (tid >= 64 && tid < 96) {
                int rr = (tid - 64) >> 2, jj = tid & 3;
                float s = 0.f;
                for (int cc = 0; cc < 64; cc++) s += Wg[rr * 64 + cc] * W1[cc * 4 + jj];
                d_wgp[rr][jj] = s;
            } else if (tid >= 96 && tid < 104) {
                int rr = tid - 96;
                float s = bg[rr];
                for (int cc = 0; cc < 64; cc++) s += Wg[rr * 64 + cc] * b1[cc];
                d_bgp[rr] = s;
            }
        }
    }

    gsync(&d_c2, GRID);

    // ---- phase 3: streaming pass. b = bid>>8, 256 px/block ----
    {
        // skp[8][65]f4 @0 (8320B); skb4[8][17]f4 @8320 (2176B); sgw @10496; sgb @10624
        float4 (*skp)[C_ + 1] = (float4(*)[C_ + 1])buf;
        float4 (*skb4)[17]    = (float4(*)[17])(buf + 8320);
        float4* sgw = (float4*)(buf + 10496);
        float*  sgb = (float*)(buf + 10624);
        int b = bid >> 8;
        int p = (bid & 255) * 256 + tid;

        // input loads first (longest latency), hidden behind smem fill
        const float* base = rgb + (size_t)b * 3 * HW;
        float x0 = base[p];
        float x1 = base[HW + p];
        float x2 = base[2 * HW + p];
        float x3 = edge[(size_t)b * HW + p];

        const float4* kps = (const float4*)&d_kp4[b][0][0][0];
#pragma unroll
        for (int it = 0; it < 2; it++) {
            int idx = tid + it * 256;
            skp[idx >> 6][idx & 63] = kps[idx];
        }
        if (tid < 128) {                                 // 8 regions x 16 float4 of bias
            const float4* kbs = (const float4*)&d_kb4[b][0][0];
            skb4[tid >> 4][tid & 15] = kbs[tid];
        }
        if (tid < 8) {
            sgw[tid] = *(const float4*)d_wgp[tid];
            sgb[tid] = d_bgp[tid];
        }
        __syncthreads();

        // argmax over 8 regions (strict > keeps first max, matching jnp.argmax)
        float best = -3.4e38f; int ri = 0;
#pragma unroll
        for (int r = 0; r < 8; r++) {
            float4 w = sgw[r];
            float gv = sgb[r] + w.x * x0 + w.y * x1 + w.z * x2 + w.w * x3;
            if (gv > best) { best = gv; ri = r; }
        }

        const float4* wrow = &skp[ri][0];
        const float4* brow = &skb4[ri][0];
        float* op = out + (size_t)b * 64 * HW + p;
        for (int gI = 0; gI < 16; gI++) {                // 4 channels / group
            float4 bb = brow[gI];
            float4 w0 = wrow[4 * gI + 0];
            float4 w1 = wrow[4 * gI + 1];
            float4 w2 = wrow[4 * gI + 2];
            float4 w3 = wrow[4 * gI + 3];
            float* o = op + (size_t)(4 * gI) * HW;
            o[0]      = bb.x + w0.x * x0 + w0.y * x1 + w0.z * x2 + w0.w * x3;
            o[HW]     = bb.y + w1.x * x0 + w1.y * x1 + w1.z * x2 + w1.w * x3;
            o[2 * HW] = bb.z + w2.x * x0 + w2.y * x1 + w2.z * x2 + w2.w * x3;
            o[3 * HW] = bb.w + w3.x * x0 + w3.y * x1 + w3.z * x2 + w3.w * x3;
        }
    }

    // ---- reset counters for next graph replay: last arriver cleans up ----
    __syncthreads();
    if (tid == 0) {
        int t = atomicAdd(&d_c3, 1);
        if (t == GRID - 1) {         // everyone has passed both spins and finished
            d_c1 = 0; d_c2 = 0;
            __threadfence();
            d_c3 = 0;
        }
    }
}

// ---------------- launch ----------------
extern "C" void kernel_launch(void* const* d_in, const int* in_sizes, int n_in,
                              void* d_out, int out_size) {
    const float* rgb  = (const float*)d_in[0];
    const float* edge = (const float*)d_in[1];
    const float* W1   = (const float*)d_in[2];
    const float* b1   = (const float*)d_in[3];
    const float* Wk1  = (const float*)d_in[4];
    const float* bk1  = (const float*)d_in[5];
    const float* Wk2  = (const float*)d_in[6];
    const float* bk2  = (const float*)d_in[7];
    const float* Wg   = (const float*)d_in[8];
    const float* bg   = (const float*)d_in[9];
    float* out = (float*)d_out;

    fused_kernel<<<GRID, 256>>>(rgb, edge, W1, b1, Wk1, bk1, Wk2, bk2, Wg, bg, out);
}

// round 12
// speedup vs baseline: 1.3402x; 1.3402x over previous
#include <cuda_runtime.h>
#include <cuda_fp16.h>
#include <math.h>

#define HW 65536
#define C_ 64
#define R_ 8
#define B_ 4

// ---------------- device scratch (no allocations allowed) ----------------
__device__ int d_c1 = 0, d_c2 = 0;                       // grid-sync counters (self-resetting)
__device__ float d_partial[16][16];                      // [plane=(b*4+i)][chunk]
__device__ __align__(16) uint2 d_kph[B_][R_][C_];        // folded weights, half4 per channel
__device__ __align__(16) uint2 d_kbh[B_][R_][16];        // folded bias, half4 per 4 channels
__device__ __align__(16) float d_wgp[R_][4];             // Wg @ W1 (fp32: argmax exactness)
__device__ float d_bgp[R_];                              // Wg @ b1 + bg

__device__ __forceinline__ uint2 pack_half4(float a0, float a1, float a2, float a3) {
    __half2 lo = __floats2half2_rn(a0, a1);
    __half2 hi = __floats2half2_rn(a2, a3);
    uint2 q;
    q.x = *reinterpret_cast<unsigned*>(&lo);
    q.y = *reinterpret_cast<unsigned*>(&hi);
    return q;
}

// ---------------- 1) fused setup: reduce -> counter sync -> kernel generation ----------------
// 256 blocks x 256 threads: all co-resident (<=2 blocks/SM), counter spin is safe.
__global__ void __launch_bounds__(256) setup_fused(
        const float* __restrict__ rgb, const float* __restrict__ edge,
        const float* __restrict__ W1, const float* __restrict__ b1,
        const float* __restrict__ Wk1, const float* __restrict__ bk1,
        const float* __restrict__ Wk2, const float* __restrict__ bk2,
        const float* __restrict__ Wg, const float* __restrict__ bg) {
    int tid = threadIdx.x, bid = blockIdx.x;

    // ---- phase 1: reduce. plane = bid>>4 (0..15), chunk = bid&15 ----
    {
        int plane = bid >> 4, chunk = bid & 15;
        int pb = plane >> 2, i = plane & 3;
        const float* src = (i < 3) ? (rgb + (size_t)(pb * 3 + i) * HW)
                                   : (edge + (size_t)pb * HW);
        const float4* p = (const float4*)src + chunk * 1024;
        float s = 0.f;
#pragma unroll
        for (int k = 0; k < 4; k++) {
            float4 v = p[tid + k * 256];
            s += (v.x + v.y) + (v.z + v.w);
        }
#pragma unroll
        for (int off = 16; off; off >>= 1) s += __shfl_down_sync(0xFFFFFFFFu, s, off);
        __shared__ float ws[8];
        if ((tid & 31) == 0) ws[tid >> 5] = s;
        __syncthreads();
        if (tid == 0) {
            float t = ws[0];
#pragma unroll
            for (int w = 1; w < 8; w++) t += ws[w];
            d_partial[plane][chunk] = t;
            __threadfence();
            atomicAdd(&d_c1, 1);
        }
    }

    // ---- grid sync: wait until all 256 blocks published their partials ----
    if (tid == 0) {
        while (atomicAdd(&d_c1, 0) < 256) __nanosleep(32);
    }
    __syncthreads();
    __threadfence();

    // ---- phase 2: blocks 0..31 generate the folded kernels ----
    if (bid < 32) {
        __shared__ float m4[4], g[64], tg[8];
        __shared__ float kern[4096];
        int b = bid >> 3, r = bid & 7;

        if (tid < 4) {
            float s = 0.f;
#pragma unroll
            for (int ch = 0; ch < 16; ch++) s += d_partial[b * 4 + tid][ch];
            m4[tid] = s * (1.0f / 65536.0f);
        }
        __syncthreads();
        if (tid < 64) {
            g[tid] = b1[tid] + W1[tid * 4 + 0] * m4[0] + W1[tid * 4 + 1] * m4[1]
                             + W1[tid * 4 + 2] * m4[2] + W1[tid * 4 + 3] * m4[3];
        }
        __syncthreads();
        if (tid < 8) {
            int row = r * 8 + tid;
            float a = bk1[row];
#pragma unroll 8
            for (int c = 0; c < 64; c++) a += Wk1[row * 64 + c] * g[c];
            tg[tid] = 1.f / (1.f + expf(-a));
        }
        __syncthreads();

        const float4* w2 = (const float4*)(Wk2 + (size_t)r * 4096 * 8);
        const float* bk = bk2 + r * 4096;
        float t0 = tg[0], t1 = tg[1], t2 = tg[2], t3 = tg[3];
        float t4 = tg[4], t5 = tg[5], t6 = tg[6], t7 = tg[7];
#pragma unroll
        for (int it = 0; it < 16; it++) {
            int o = tid + it * 256;
            float4 wa = w2[o * 2], wb = w2[o * 2 + 1];
            kern[o] = bk[o] + t0 * wa.x + t1 * wa.y + t2 * wa.z + t3 * wa.w
                            + t4 * wb.x + t5 * wb.y + t6 * wb.z + t7 * wb.w;
        }
        __syncthreads();

        // fold through W1 (comp j of channel c) and b1; pack to fp16
        int c = tid >> 2, j = tid & 3;                   // 64 x 4 threads
        float acc = 0.f;
#pragma unroll 8
        for (int ci = 0; ci < 64; ci++) acc += kern[c * 64 + ci] * W1[ci * 4 + j];
        float ab = 0.f;                                  // bias (same for all j of this c)
#pragma unroll 8
        for (int ci = 0; ci < 64; ci++) ab += kern[c * 64 + ci] * b1[ci];

        unsigned m = 0xFFFFFFFFu;
        float a1 = __shfl_down_sync(m, acc, 1);
        float a2 = __shfl_down_sync(m, acc, 2);
        float a3 = __shfl_down_sync(m, acc, 3);
        if (j == 0) d_kph[b][r][c] = pack_half4(acc, a1, a2, a3);   // w0..w3 of channel c

        float b1v = __shfl_down_sync(m, ab, 4);
        float b2v = __shfl_down_sync(m, ab, 8);
        float b3v = __shfl_down_sync(m, ab, 12);
        if ((tid & 15) == 0)                              // channels c, c+1, c+2, c+3
            d_kbh[b][r][tid >> 4] = pack_half4(ab, b1v, b2v, b3v);

        if (bid == 0) {                                  // folded guide weights (fp32)
            if (tid >= 64 && tid < 96) {
                int rr = (tid - 64) >> 2, jj = tid & 3;
                float s = 0.f;
                for (int cc = 0; cc < 64; cc++) s += Wg[rr * 64 + cc] * W1[cc * 4 + jj];
                d_wgp[rr][jj] = s;
            } else if (tid >= 96 && tid < 104) {
                int rr = tid - 96;
                float s = bg[rr];
                for (int cc = 0; cc < 64; cc++) s += Wg[rr * 64 + cc] * b1[cc];
                d_bgp[rr] = s;
            }
        }
    }

    // ---- reset counters for next graph replay ----
    __syncthreads();
    if (tid == 0) {
        int t = atomicAdd(&d_c2, 1);
        if (t == 255) {
            d_c1 = 0;
            __threadfence();
            d_c2 = 0;
        }
    }
}

// ---------------- 2) streaming main pass: argmax + fp16-weight 64x5 matvec ----------------
// 1 px/thread, 256 thr/block, grid (256,4). Weight row stride 65 uint2:
// LDS.64 bank = (2r + 2c) mod 32 -> the 8 regions land in disjoint banks, conflict-free.
__global__ void __launch_bounds__(256, 7) main_kernel(const float* __restrict__ rgb,
                                                      const float* __restrict__ edge,
                                                      float* __restrict__ out) {
    __shared__ __align__(16) uint2 skh[R_][C_ + 1];      // half4 weights per channel
    __shared__ __align__(16) uint2 skbh[R_][17];         // half4 bias per 4 channels
    __shared__ float4 sgw[R_];
    __shared__ float  sgb[R_];
    int tid = threadIdx.x;
    int b = blockIdx.y;
    int p = blockIdx.x * 256 + tid;

    // input loads first (longest latency), hidden behind smem fill
    const float* base = rgb + (size_t)b * 3 * HW;
    float x0 = base[p];
    float x1 = base[HW + p];
    float x2 = base[2 * HW + p];
    float x3 = edge[(size_t)b * HW + p];

    const uint2* kps = &d_kph[b][0][0];
#pragma unroll
    for (int it = 0; it < 2; it++) {
        int idx = tid + it * 256;
        skh[idx >> 6][idx & 63] = kps[idx];
    }
    if (tid < 128) {
        const uint2* kbs = &d_kbh[b][0][0];
        skbh[tid >> 4][tid & 15] = kbs[tid];
    }
    if (tid < 8) {
        sgw[tid] = *(const float4*)d_wgp[tid];
        sgb[tid] = d_bgp[tid];
    }
    __syncthreads();

    // argmax over 8 regions in fp32 (strict > keeps first max, matching jnp.argmax)
    float best = -3.4e38f; int ri = 0;
#pragma unroll
    for (int r = 0; r < 8; r++) {
        float4 w = sgw[r];
        float gv = sgb[r] + w.x * x0 + w.y * x1 + w.z * x2 + w.w * x3;
        if (gv > best) { best = gv; ri = r; }
    }

    const uint2* wrow = &skh[ri][0];
    const uint2* brow = &skbh[ri][0];
    float* op = out + (size_t)b * 64 * HW + p;
#pragma unroll
    for (int g = 0; g < 16; g++) {                       // 4 channels per group
        uint2 bq = brow[g];
        float2 bb01 = __half22float2(*reinterpret_cast<__half2*>(&bq.x));
        float2 bb23 = __half22float2(*reinterpret_cast<__half2*>(&bq.y));
        float* o = op + (size_t)(4 * g) * HW;
#pragma unroll
        for (int cc = 0; cc < 4; cc++) {
            uint2 q = wrow[4 * g + cc];
            float2 w01 = __half22float2(*reinterpret_cast<__half2*>(&q.x));
            float2 w23 = __half22float2(*reinterpret_cast<__half2*>(&q.y));
            float bias = (cc < 2) ? ((cc == 0) ? bb01.x : bb01.y)
                                  : ((cc == 2) ? bb23.x : bb23.y);
            o[(size_t)cc * HW] = bias + w01.x * x0 + w01.y * x1 + w23.x * x2 + w23.y * x3;
        }
    }
}

// ---------------- launch ----------------
extern "C" void kernel_launch(void* const* d_in, const int* in_sizes, int n_in,
                              void* d_out, int out_size) {
    const float* rgb  = (const float*)d_in[0];
    const float* edge = (const float*)d_in[1];
    const float* W1   = (const float*)d_in[2];
    const float* b1   = (const float*)d_in[3];
    const float* Wk1  = (const float*)d_in[4];
    const float* bk1  = (const float*)d_in[5];
    const float* Wk2  = (const float*)d_in[6];
    const float* bk2  = (const float*)d_in[7];
    const float* Wg   = (const float*)d_in[8];
    const float* bg   = (const float*)d_in[9];
    float* out = (float*)d_out;

    setup_fused<<<256, 256>>>(rgb, edge, W1, b1, Wk1, bk1, Wk2, bk2, Wg, bg);
    main_kernel<<<dim3(256, B_), 256>>>(rgb, edge, out);
}

// round 13
// speedup vs baseline: 1.5549x; 1.1602x over previous
#include <cuda_runtime.h>
#include <cuda_fp16.h>
#include <math.h>

#define HW 65536
#define C_ 64
#define R_ 8
#define B_ 4

// ---------------- device scratch (no allocations allowed) ----------------
__device__ int d_c1 = 0, d_c2 = 0;                       // grid-sync counters (self-resetting)
__device__ float d_partial[16][16];                      // [plane=(b*4+i)][chunk]
__device__ __align__(16) __half2 d_kw[B_][R_][32][4];    // [pair c/2][j] : (w_j[2p], w_j[2p+1])
__device__ __align__(16) uint4 d_kb[B_][R_][8];          // per 8-ch group: 4 bias half2
__device__ __align__(16) float d_wgp[R_][4];             // Wg @ W1 (fp32: argmax exactness)
__device__ float d_bgp[R_];                              // Wg @ b1 + bg

// ---------------- 1) fused setup: reduce -> counter sync -> spread kernel generation ----------------
// 256 blocks x 256 threads: all co-resident, counter spin is safe.
__global__ void __launch_bounds__(256) setup_fused(
        const float* __restrict__ rgb, const float* __restrict__ edge,
        const float* __restrict__ W1, const float* __restrict__ b1,
        const float* __restrict__ Wk1, const float* __restrict__ bk1,
        const float* __restrict__ Wk2, const float* __restrict__ bk2,
        const float* __restrict__ Wg, const float* __restrict__ bg) {
    int tid = threadIdx.x, bid = blockIdx.x;

    // ---- phase 1: reduce. plane = bid>>4 (0..15), chunk = bid&15 ----
    {
        int plane = bid >> 4, chunk = bid & 15;
        int pb = plane >> 2, i = plane & 3;
        const float* src = (i < 3) ? (rgb + (size_t)(pb * 3 + i) * HW)
                                   : (edge + (size_t)pb * HW);
        const float4* p = (const float4*)src + chunk * 1024;
        float s = 0.f;
#pragma unroll
        for (int k = 0; k < 4; k++) {
            float4 v = p[tid + k * 256];
            s += (v.x + v.y) + (v.z + v.w);
        }
#pragma unroll
        for (int off = 16; off; off >>= 1) s += __shfl_down_sync(0xFFFFFFFFu, s, off);
        __shared__ float ws[8];
        if ((tid & 31) == 0) ws[tid >> 5] = s;
        __syncthreads();
        if (tid == 0) {
            float t = ws[0];
#pragma unroll
            for (int w = 1; w < 8; w++) t += ws[w];
            d_partial[plane][chunk] = t;
            __threadfence();
            atomicAdd(&d_c1, 1);
        }
    }

    // ---- grid sync ----
    if (tid == 0) {
        while (atomicAdd(&d_c1, 0) < 256) __nanosleep(32);
    }
    __syncthreads();
    __threadfence();

    // ---- phase 2 (ALL 256 blocks): b = bid>>6, r = (bid>>3)&7, part = bid&7 ----
    // each block builds channels [8*part, 8*part+8) of the folded kernel for (b, r)
    {
        __shared__ float m4[4], g[64], tg[8];
        __shared__ float skern[512];                     // 8 channels x 64 ci
        __shared__ float sfold[8][5];                    // [c_loc][w0..w3, bias]
        int b = bid >> 6, r = (bid >> 3) & 7, part = bid & 7;

        if (tid < 4) {
            float s = 0.f;
#pragma unroll
            for (int ch = 0; ch < 16; ch++) s += d_partial[b * 4 + tid][ch];
            m4[tid] = s * (1.0f / 65536.0f);
        }
        __syncthreads();
        if (tid < 64) {
            g[tid] = b1[tid] + W1[tid * 4 + 0] * m4[0] + W1[tid * 4 + 1] * m4[1]
                             + W1[tid * 4 + 2] * m4[2] + W1[tid * 4 + 3] * m4[3];
        }
        __syncthreads();
        if (tid < 8) {
            int row = r * 8 + tid;
            float a = bk1[row];
#pragma unroll 8
            for (int c = 0; c < 64; c++) a += Wk1[row * 64 + c] * g[c];
            tg[tid] = 1.f / (1.f + expf(-a));
        }
        __syncthreads();

        float t0 = tg[0], t1 = tg[1], t2 = tg[2], t3 = tg[3];
        float t4 = tg[4], t5 = tg[5], t6 = tg[6], t7 = tg[7];
#pragma unroll
        for (int it = 0; it < 2; it++) {
            int e = tid + it * 256;                      // 0..511
            int o = part * 512 + e;                      // global co*64+ci within (r)
            const float4* w2 = (const float4*)(Wk2 + ((size_t)r * 4096 + o) * 8);
            float4 wa = w2[0], wb = w2[1];
            skern[e] = bk2[r * 4096 + o]
                     + t0 * wa.x + t1 * wa.y + t2 * wa.z + t3 * wa.w
                     + t4 * wb.x + t5 * wb.y + t6 * wb.z + t7 * wb.w;
        }
        __syncthreads();

        if (tid < 40) {                                  // fold through W1 / b1
            int cl = tid / 5, k = tid % 5;
            float s = 0.f;
            if (k < 4) {
#pragma unroll 8
                for (int ci = 0; ci < 64; ci++) s += skern[cl * 64 + ci] * W1[ci * 4 + k];
            } else {
#pragma unroll 8
                for (int ci = 0; ci < 64; ci++) s += skern[cl * 64 + ci] * b1[ci];
            }
            sfold[cl][k] = s;
        }
        __syncthreads();

        if (tid < 16) {                                  // pack weight half2 pairs
            int pp = tid >> 2, j = tid & 3;              // local pair 0..3, comp j
            d_kw[b][r][part * 4 + pp][j] =
                __floats2half2_rn(sfold[2 * pp][j], sfold[2 * pp + 1][j]);
        } else if (tid == 16) {                          // pack 8 biases -> uint4
            uint4 q;
            __half2 h0 = __floats2half2_rn(sfold[0][4], sfold[1][4]);
            __half2 h1 = __floats2half2_rn(sfold[2][4], sfold[3][4]);
            __half2 h2 = __floats2half2_rn(sfold[4][4], sfold[5][4]);
            __half2 h3 = __floats2half2_rn(sfold[6][4], sfold[7][4]);
            q.x = *reinterpret_cast<unsigned*>(&h0);
            q.y = *reinterpret_cast<unsigned*>(&h1);
            q.z = *reinterpret_cast<unsigned*>(&h2);
            q.w = *reinterpret_cast<unsigned*>(&h3);
            d_kb[b][r][part] = q;
        }

        if (bid == 0) {                                  // folded guide weights (fp32)
            if (tid >= 64 && tid < 96) {
                int rr = (tid - 64) >> 2, jj = tid & 3;
                float s = 0.f;
                for (int cc = 0; cc < 64; cc++) s += Wg[rr * 64 + cc] * W1[cc * 4 + jj];
                d_wgp[rr][jj] = s;
            } else if (tid >= 96 && tid < 104) {
                int rr = tid - 96;
                float s = bg[rr];
                for (int cc = 0; cc < 64; cc++) s += Wg[rr * 64 + cc] * b1[cc];
                d_bgp[rr] = s;
            }
        }
    }

    // ---- reset counters for next graph replay ----
    __syncthreads();
    if (tid == 0) {
        int t = atomicAdd(&d_c2, 1);
        if (t == 255) {
            d_c1 = 0;
            __threadfence();
            d_c2 = 0;
        }
    }
}

// ---------------- 2) streaming main pass: fp32 argmax + HFMA2 fp16 matvec ----------------
// 1 px/thread, 256 thr/block, grid (256,4). Conflict-free: region strides 528B / 144B
// give LDS.128 start banks (4r+4P) / (4r+4g) mod 32 -> 8 regions disjoint.
__global__ void __launch_bounds__(256, 7) main_kernel(const float* __restrict__ rgb,
                                                      const float* __restrict__ edge,
                                                      float* __restrict__ out) {
    __shared__ __align__(16) __half2 skw[R_][33][4];     // weight pairs, padded stride
    __shared__ __align__(16) uint4 skb[R_][9];           // bias groups, padded stride
    __shared__ float4 sgw[R_];
    __shared__ float  sgb[R_];
    int tid = threadIdx.x;
    int b = blockIdx.y;
    int p = blockIdx.x * 256 + tid;

    // input loads first (longest latency), hidden behind smem fill
    const float* base = rgb + (size_t)b * 3 * HW;
    float x0 = base[p];
    float x1 = base[HW + p];
    float x2 = base[2 * HW + p];
    float x3 = edge[(size_t)b * HW + p];

    {   // weights: 8 regions x 32 pairs x 16B = 256 uint4
        const uint4* src = (const uint4*)&d_kw[b][0][0][0];
        int r = tid >> 5, pr = tid & 31;
        *reinterpret_cast<uint4*>(&skw[r][pr][0]) = src[tid];
    }
    if (tid < 64) {                                      // bias: 8 regions x 8 uint4
        const uint4* src = (const uint4*)&d_kb[b][0][0];
        skb[tid >> 3][tid & 7] = src[tid];
    }
    if (tid < 8) {
        sgw[tid] = *(const float4*)d_wgp[tid];
        sgb[tid] = d_bgp[tid];
    }
    __syncthreads();

    // argmax over 8 regions in fp32 (strict > keeps first max, matching jnp.argmax)
    float best = -3.4e38f; int ri = 0;
#pragma unroll
    for (int r = 0; r < 8; r++) {
        float4 w = sgw[r];
        float gv = sgb[r] + w.x * x0 + w.y * x1 + w.z * x2 + w.w * x3;
        if (gv > best) { best = gv; ri = r; }
    }

    // duplicate inputs into half2
    __half2 hx0 = __float2half2_rn(x0);
    __half2 hx1 = __float2half2_rn(x1);
    __half2 hx2 = __float2half2_rn(x2);
    __half2 hx3 = __float2half2_rn(x3);

    float* op = out + (size_t)b * 64 * HW + p;
#pragma unroll
    for (int g = 0; g < 8; g++) {                        // 8 channels per group
        uint4 bq = skb[ri][g];
        const __half2* bh = reinterpret_cast<const __half2*>(&bq);
#pragma unroll
        for (int pp = 0; pp < 4; pp++) {                 // channel pair (8g+2pp, +1)
            uint4 wq = *reinterpret_cast<const uint4*>(&skw[ri][4 * g + pp][0]);
            const __half2* wh = reinterpret_cast<const __half2*>(&wq);
            __half2 acc = bh[pp];
            acc = __hfma2(wh[0], hx0, acc);
            acc = __hfma2(wh[1], hx1, acc);
            acc = __hfma2(wh[2], hx2, acc);
            acc = __hfma2(wh[3], hx3, acc);
            float2 y = __half22float2(acc);
            float* o = op + (size_t)(8 * g + 2 * pp) * HW;
            o[0]  = y.x;
            o[HW] = y.y;
        }
    }
}

// ---------------- launch ----------------
extern "C" void kernel_launch(void* const* d_in, const int* in_sizes, int n_in,
                              void* d_out, int out_size) {
    const float* rgb  = (const float*)d_in[0];
    const float* edge = (const float*)d_in[1];
    const float* W1   = (const float*)d_in[2];
    const float* b1   = (const float*)d_in[3];
    const float* Wk1  = (const float*)d_in[4];
    const float* bk1  = (const float*)d_in[5];
    const float* Wk2  = (const float*)d_in[6];
    const float* bk2  = (const float*)d_in[7];
    const float* Wg   = (const float*)d_in[8];
    const float* bg   = (const float*)d_in[9];
    float* out = (float*)d_out;

    setup_fused<<<256, 256>>>(rgb, edge, W1, b1, Wk1, bk1, Wk2, bk2, Wg, bg);
    main_kernel<<<dim3(256, B_), 256>>>(rgb, edge, out);
}

// round 14
// speedup vs baseline: 1.5588x; 1.0025x over previous
#include <cuda_runtime.h>
#include <cuda_fp16.h>
#include <math.h>

#define HW 65536
#define C_ 64
#define R_ 8
#define B_ 4
#define SGRID 512

// ---------------- device scratch (no allocations allowed) ----------------
__device__ int d_c1 = 0, d_c2 = 0;                       // grid-sync counters (self-resetting)
__device__ float d_partial[16][32];                      // [plane=(b*4+i)][chunk]
__device__ __align__(16) uint4 d_kw[B_][R_][32];         // weight pair quads (half2 x4)
__device__ __align__(16) uint4 d_kb[B_][R_][8];          // per 8-ch group: 4 bias half2
__device__ __align__(16) float d_wgp[R_][4];             // Wg @ W1 (fp32: argmax exactness)
__device__ float d_bgp[R_];                              // Wg @ b1 + bg

// ---------------- 1) fused setup: reduce -> counter sync -> spread kernel generation ----------------
// 512 blocks x 256 threads: all co-resident (4 blk/SM x 8 warps = 32 warps), spin is safe.
__global__ void __launch_bounds__(256) setup_fused(
        const float* __restrict__ rgb, const float* __restrict__ edge,
        const float* __restrict__ W1, const float* __restrict__ b1,
        const float* __restrict__ Wk1, const float* __restrict__ bk1,
        const float* __restrict__ Wk2, const float* __restrict__ bk2,
        const float* __restrict__ Wg, const float* __restrict__ bg) {
    int tid = threadIdx.x, bid = blockIdx.x;

    // ---- phase 1: reduce. plane = bid>>5 (0..15), chunk = bid&31 ----
    {
        int plane = bid >> 5, chunk = bid & 31;
        int pb = plane >> 2, i = plane & 3;
        const float* src = (i < 3) ? (rgb + (size_t)(pb * 3 + i) * HW)
                                   : (edge + (size_t)pb * HW);
        const float4* p = (const float4*)src + chunk * 512;
        float4 v0 = p[tid];
        float4 v1 = p[tid + 256];
        float s = ((v0.x + v0.y) + (v0.z + v0.w)) + ((v1.x + v1.y) + (v1.z + v1.w));
#pragma unroll
        for (int off = 16; off; off >>= 1) s += __shfl_down_sync(0xFFFFFFFFu, s, off);
        __shared__ float ws[8];
        if ((tid & 31) == 0) ws[tid >> 5] = s;
        __syncthreads();
        if (tid == 0) {
            float t = ws[0];
#pragma unroll
            for (int w = 1; w < 8; w++) t += ws[w];
            d_partial[plane][chunk] = t;
            __threadfence();
            atomicAdd(&d_c1, 1);
        }
    }

    // ---- grid sync ----
    if (tid == 0) {
        while (atomicAdd(&d_c1, 0) < SGRID) __nanosleep(32);
    }
    __syncthreads();
    __threadfence();

    // ---- phase 2 (blocks 0..255): b = bid>>6, r = (bid>>3)&7, part = bid&7 ----
    // each block builds channels [8*part, 8*part+8) of the folded kernel for (b, r)
    if (bid < 256) {
        __shared__ float m4[4], g[64], tg[8];
        __shared__ float skern[512];                     // 8 channels x 64 ci
        __shared__ float sfold[8][5];                    // [c_loc][w0..w3, bias]
        int b = bid >> 6, r = (bid >> 3) & 7, part = bid & 7;

        if (tid < 4) {
            float s = 0.f;
#pragma unroll
            for (int ch = 0; ch < 32; ch++) s += d_partial[b * 4 + tid][ch];
            m4[tid] = s * (1.0f / 65536.0f);
        }
        __syncthreads();
        if (tid < 64) {
            g[tid] = b1[tid] + W1[tid * 4 + 0] * m4[0] + W1[tid * 4 + 1] * m4[1]
                             + W1[tid * 4 + 2] * m4[2] + W1[tid * 4 + 3] * m4[3];
        }
        __syncthreads();
        if (tid < 8) {
            int row = r * 8 + tid;
            float a = bk1[row];
#pragma unroll 8
            for (int c = 0; c < 64; c++) a += Wk1[row * 64 + c] * g[c];
            tg[tid] = 1.f / (1.f + expf(-a));
        }
        __syncthreads();

        float t0 = tg[0], t1 = tg[1], t2 = tg[2], t3 = tg[3];
        float t4 = tg[4], t5 = tg[5], t6 = tg[6], t7 = tg[7];
#pragma unroll
        for (int it = 0; it < 2; it++) {
            int e = tid + it * 256;                      // 0..511
            int o = part * 512 + e;                      // global co*64+ci within (r)
            const float4* w2 = (const float4*)(Wk2 + ((size_t)r * 4096 + o) * 8);
            float4 wa = w2[0], wb = w2[1];
            skern[e] = bk2[r * 4096 + o]
                     + t0 * wa.x + t1 * wa.y + t2 * wa.z + t3 * wa.w
                     + t4 * wb.x + t5 * wb.y + t6 * wb.z + t7 * wb.w;
        }
        __syncthreads();

        if (tid < 40) {                                  // fold through W1 / b1
            int cl = tid / 5, k = tid % 5;
            float s = 0.f;
            if (k < 4) {
#pragma unroll 8
                for (int ci = 0; ci < 64; ci++) s += skern[cl * 64 + ci] * W1[ci * 4 + k];
            } else {
#pragma unroll 8
                for (int ci = 0; ci < 64; ci++) s += skern[cl * 64 + ci] * b1[ci];
            }
            sfold[cl][k] = s;
        }
        __syncthreads();

        if (tid < 4) {                                   // pack 4 weight quads (one per pair)
            int pp = tid;                                // local pair 0..3
            __half2 h0 = __floats2half2_rn(sfold[2 * pp][0], sfold[2 * pp + 1][0]);
            __half2 h1 = __floats2half2_rn(sfold[2 * pp][1], sfold[2 * pp + 1][1]);
            __half2 h2 = __floats2half2_rn(sfold[2 * pp][2], sfold[2 * pp + 1][2]);
            __half2 h3 = __floats2half2_rn(sfold[2 * pp][3], sfold[2 * pp + 1][3]);
            uint4 q;
            q.x = *reinterpret_cast<unsigned*>(&h0);
            q.y = *reinterpret_cast<unsigned*>(&h1);
            q.z = *reinterpret_cast<unsigned*>(&h2);
            q.w = *reinterpret_cast<unsigned*>(&h3);
            d_kw[b][r][part * 4 + pp] = q;
        } else if (tid == 4) {                           // pack 8 biases -> uint4
            uint4 q;
            __half2 h0 = __floats2half2_rn(sfold[0][4], sfold[1][4]);
            __half2 h1 = __floats2half2_rn(sfold[2][4], sfold[3][4]);
            __half2 h2 = __floats2half2_rn(sfold[4][4], sfold[5][4]);
            __half2 h3 = __floats2half2_rn(sfold[6][4], sfold[7][4]);
            q.x = *reinterpret_cast<unsigned*>(&h0);
            q.y = *reinterpret_cast<unsigned*>(&h1);
            q.z = *reinterpret_cast<unsigned*>(&h2);
            q.w = *reinterpret_cast<unsigned*>(&h3);
            d_kb[b][r][part] = q;
        }

        if (bid == 0) {                                  // folded guide weights (fp32)
            if (tid >= 64 && tid < 96) {
                int rr = (tid - 64) >> 2, jj = tid & 3;
                float s = 0.f;
                for (int cc = 0; cc < 64; cc++) s += Wg[rr * 64 + cc] * W1[cc * 4 + jj];
                d_wgp[rr][jj] = s;
            } else if (tid >= 96 && tid < 104) {
                int rr = tid - 96;
                float s = bg[rr];
                for (int cc = 0; cc < 64; cc++) s += Wg[rr * 64 + cc] * b1[cc];
                d_bgp[rr] = s;
            }
        }
    }

    // ---- reset counters for next graph replay ----
    __syncthreads();
    if (tid == 0) {
        int t = atomicAdd(&d_c2, 1);
        if (t == SGRID - 1) {
            d_c1 = 0;
            __threadfence();
            d_c2 = 0;
        }
    }
}

// ---------------- 2) streaming main pass: fp32 argmax + HFMA2 fp16 matvec ----------------
// 1 px/thread, 256 thr/block, grid (256,4). launch_bounds(256,5) ~= 51 regs so ptxas can
// software-pipeline the per-group loads. Conflict-free: region strides 528B / 144B give
// LDS.128 start banks (4r+4idx) mod 32 -> the 8 regions land disjoint.
__global__ void __launch_bounds__(256, 5) main_kernel(const float* __restrict__ rgb,
                                                      const float* __restrict__ edge,
                                                      float* __restrict__ out) {
    __shared__ __align__(16) uint4 skw[R_][33];          // weight pair quads, padded stride
    __shared__ __align__(16) uint4 skb[R_][9];           // bias groups, padded stride
    __shared__ float4 sgw[R_];
    __shared__ float  sgb[R_];
    int tid = threadIdx.x;
    int b = blockIdx.y;
    int p = blockIdx.x * 256 + tid;

    // input loads first (longest latency), hidden behind smem fill
    const float* base = rgb + (size_t)b * 3 * HW;
    float x0 = base[p];
    float x1 = base[HW + p];
    float x2 = base[2 * HW + p];
    float x3 = edge[(size_t)b * HW + p];

    {   // weights: 8 regions x 32 quads = 256 uint4
        const uint4* src = &d_kw[b][0][0];
        skw[tid >> 5][tid & 31] = src[tid];
    }
    if (tid < 64) {                                      // bias: 8 regions x 8 uint4
        const uint4* src = &d_kb[b][0][0];
        skb[tid >> 3][tid & 7] = src[tid];
    }
    if (tid < 8) {
        sgw[tid] = *(const float4*)d_wgp[tid];
        sgb[tid] = d_bgp[tid];
    }
    __syncthreads();

    // argmax over 8 regions in fp32 (strict > keeps first max, matching jnp.argmax)
    float best = -3.4e38f; int ri = 0;
#pragma unroll
    for (int r = 0; r < 8; r++) {
        float4 w = sgw[r];
        float gv = sgb[r] + w.x * x0 + w.y * x1 + w.z * x2 + w.w * x3;
        if (gv > best) { best = gv; ri = r; }
    }

    // duplicate inputs into half2
    __half2 hx0 = __float2half2_rn(x0);
    __half2 hx1 = __float2half2_rn(x1);
    __half2 hx2 = __float2half2_rn(x2);
    __half2 hx3 = __float2half2_rn(x3);

    const uint4* wrow = &skw[ri][0];
    const uint4* brow = &skb[ri][0];
    float* op = out + (size_t)b * 64 * HW + p;
#pragma unroll 2
    for (int g = 0; g < 8; g++) {                        // 8 channels per group
        // batch all 5 independent LDS.128 for this group up front
        uint4 bq  = brow[g];
        uint4 wq0 = wrow[4 * g + 0];
        uint4 wq1 = wrow[4 * g + 1];
        uint4 wq2 = wrow[4 * g + 2];
        uint4 wq3 = wrow[4 * g + 3];
        const __half2* bh = reinterpret_cast<const __half2*>(&bq);

        __half2 a0 = bh[0], a1 = bh[1], a2 = bh[2], a3 = bh[3];
        const __half2* w0 = reinterpret_cast<const __half2*>(&wq0);
        const __half2* w1 = reinterpret_cast<const __half2*>(&wq1);
        const __half2* w2 = reinterpret_cast<const __half2*>(&wq2);
        const __half2* w3 = reinterpret_cast<const __half2*>(&wq3);
        a0 = __hfma2(w0[0], hx0, a0); a1 = __hfma2(w1[0], hx0, a1);
        a2 = __hfma2(w2[0], hx0, a2); a3 = __hfma2(w3[0], hx0, a3);
        a0 = __hfma2(w0[1], hx1, a0); a1 = __hfma2(w1[1], hx1, a1);
        a2 = __hfma2(w2[1], hx1, a2); a3 = __hfma2(w3[1], hx1, a3);
        a0 = __hfma2(w0[2], hx2, a0); a1 = __hfma2(w1[2], hx2, a1);
        a2 = __hfma2(w2[2], hx2, a2); a3 = __hfma2(w3[2], hx2, a3);
        a0 = __hfma2(w0[3], hx3, a0); a1 = __hfma2(w1[3], hx3, a1);
        a2 = __hfma2(w2[3], hx3, a2); a3 = __hfma2(w3[3], hx3, a3);

        float2 y0 = __half22float2(a0);
        float2 y1 = __half22float2(a1);
        float2 y2 = __half22float2(a2);
        float2 y3 = __half22float2(a3);
        float* o = op + (size_t)(8 * g) * HW;
        o[0]          = y0.x;  o[HW]         = y0.y;
        o[2 * HW]     = y1.x;  o[3 * HW]     = y1.y;
        o[4 * HW]     = y2.x;  o[5 * HW]     = y2.y;
        o[6 * HW]     = y3.x;  o[7 * HW]     = y3.y;
    }
}

// ---------------- launch ----------------
extern "C" void kernel_launch(void* const* d_in, const int* in_sizes, int n_in,
                              void* d_out, int out_size) {
    const float* rgb  = (const float*)d_in[0];
    const float* edge = (const float*)d_in[1];
    const float* W1   = (const float*)d_in[2];
    const float* b1   = (const float*)d_in[3];
    const float* Wk1  = (const float*)d_in[4];
    const float* bk1  = (const float*)d_in[5];
    const float* Wk2  = (const float*)d_in[6];
    const float* bk2  = (const float*)d_in[7];
    const float* Wg   = (const float*)d_in[8];
    const float* bg   = (const float*)d_in[9];
    float* out = (float*)d_out;

    setup_fused<<<SGRID, 256>>>(rgb, edge, W1, b1, Wk1, bk1, Wk2, bk2, Wg, bg);
    main_kernel<<<dim3(256, B_), 256>>>(rgb, edge, out);
}

// round 16
// speedup vs baseline: 1.5727x; 1.0089x over previous
#include <cuda_runtime.h>
#include <cuda_fp16.h>
#include <math.h>

#define HW 65536
#define C_ 64
#define R_ 8
#define B_ 4
#define SGRID 512

// ---------------- device scratch (no allocations allowed) ----------------
__device__ int d_c1 = 0, d_c2 = 0;                       // grid-sync counters (self-resetting)
__device__ float d_partial[16][32];                      // [plane=(b*4+i)][chunk]
__device__ __align__(16) uint4 d_kw[B_][R_][32];         // weight pair quads (half2 x4)
__device__ __align__(16) uint4 d_kb[B_][R_][8];          // per 8-ch group: 4 bias half2
__device__ __align__(16) float d_wgp[R_][4];             // Wg @ W1 (fp32: argmax exactness)
__device__ float d_bgp[R_];                              // Wg @ b1 + bg

// ---------------- 1) fused setup: reduce -> counter sync -> spread kernel generation ----------------
// 512 blocks x 256 threads: all co-resident (4 blk/SM x 8 warps), spin is safe.
__global__ void __launch_bounds__(256) setup_fused(
        const float* __restrict__ rgb, const float* __restrict__ edge,
        const float* __restrict__ W1, const float* __restrict__ b1,
        const float* __restrict__ Wk1, const float* __restrict__ bk1,
        const float* __restrict__ Wk2, const float* __restrict__ bk2,
        const float* __restrict__ Wg, const float* __restrict__ bg) {
    int tid = threadIdx.x, bid = blockIdx.x;

    // ---- phase 1: reduce. plane = bid>>5 (0..15), chunk = bid&31 ----
    {
        int plane = bid >> 5, chunk = bid & 31;
        int pb = plane >> 2, i = plane & 3;
        const float* src = (i < 3) ? (rgb + (size_t)(pb * 3 + i) * HW)
                                   : (edge + (size_t)pb * HW);
        const float4* p = (const float4*)src + chunk * 512;
        float4 v0 = p[tid];
        float4 v1 = p[tid + 256];
        float s = ((v0.x + v0.y) + (v0.z + v0.w)) + ((v1.x + v1.y) + (v1.z + v1.w));
#pragma unroll
        for (int off = 16; off; off >>= 1) s += __shfl_down_sync(0xFFFFFFFFu, s, off);
        __shared__ float ws[8];
        if ((tid & 31) == 0) ws[tid >> 5] = s;
        __syncthreads();
        if (tid == 0) {
            float t = ws[0];
#pragma unroll
            for (int w = 1; w < 8; w++) t += ws[w];
            d_partial[plane][chunk] = t;
            __threadfence();
            atomicAdd(&d_c1, 1);
        }
    }

    // ---- grid sync ----
    if (tid == 0) {
        while (atomicAdd(&d_c1, 0) < SGRID) __nanosleep(32);
    }
    __syncthreads();
    __threadfence();

    // ---- phase 2 (blocks 0..255): b = bid>>6, r = (bid>>3)&7, part = bid&7 ----
    if (bid < 256) {
        __shared__ float m4[4], g[64], tg[8];
        __shared__ float skern[512];                     // 8 channels x 64 ci
        __shared__ float sfold[8][5];                    // [c_loc][w0..w3, bias]
        int b = bid >> 6, r = (bid >> 3) & 7, part = bid & 7;

        if (tid < 4) {
            float s = 0.f;
#pragma unroll
            for (int ch = 0; ch < 32; ch++) s += d_partial[b * 4 + tid][ch];
            m4[tid] = s * (1.0f / 65536.0f);
        }
        __syncthreads();
        if (tid < 64) {
            g[tid] = b1[tid] + W1[tid * 4 + 0] * m4[0] + W1[tid * 4 + 1] * m4[1]
                             + W1[tid * 4 + 2] * m4[2] + W1[tid * 4 + 3] * m4[3];
        }
        __syncthreads();
        if (tid < 8) {
            int row = r * 8 + tid;
            float a = bk1[row];
#pragma unroll 8
            for (int c = 0; c < 64; c++) a += Wk1[row * 64 + c] * g[c];
            tg[tid] = 1.f / (1.f + expf(-a));
        }
        __syncthreads();

        float t0 = tg[0], t1 = tg[1], t2 = tg[2], t3 = tg[3];
        float t4 = tg[4], t5 = tg[5], t6 = tg[6], t7 = tg[7];
#pragma unroll
        for (int it = 0; it < 2; it++) {
            int e = tid + it * 256;                      // 0..511
            int o = part * 512 + e;                      // global co*64+ci within (r)
            const float4* w2 = (const float4*)(Wk2 + ((size_t)r * 4096 + o) * 8);
            float4 wa = w2[0], wb = w2[1];
            skern[e] = bk2[r * 4096 + o]
                     + t0 * wa.x + t1 * wa.y + t2 * wa.z + t3 * wa.w
                     + t4 * wb.x + t5 * wb.y + t6 * wb.z + t7 * wb.w;
        }
        __syncthreads();

        if (tid < 40) {                                  // fold through W1 / b1
            int cl = tid / 5, k = tid % 5;
            float s = 0.f;
            if (k < 4) {
#pragma unroll 8
                for (int ci = 0; ci < 64; ci++) s += skern[cl * 64 + ci] * W1[ci * 4 + k];
            } else {
#pragma unroll 8
                for (int ci = 0; ci < 64; ci++) s += skern[cl * 64 + ci] * b1[ci];
            }
            sfold[cl][k] = s;
        }
        __syncthreads();

        if (tid < 4) {                                   // pack 4 weight quads (one per pair)
            int pp = tid;
            __half2 h0 = __floats2half2_rn(sfold[2 * pp][0], sfold[2 * pp + 1][0]);
            __half2 h1 = __floats2half2_rn(sfold[2 * pp][1], sfold[2 * pp + 1][1]);
            __half2 h2 = __floats2half2_rn(sfold[2 * pp][2], sfold[2 * pp + 1][2]);
            __half2 h3 = __floats2half2_rn(sfold[2 * pp][3], sfold[2 * pp + 1][3]);
            uint4 q;
            q.x = *reinterpret_cast<unsigned*>(&h0);
            q.y = *reinterpret_cast<unsigned*>(&h1);
            q.z = *reinterpret_cast<unsigned*>(&h2);
            q.w = *reinterpret_cast<unsigned*>(&h3);
            d_kw[b][r][part * 4 + pp] = q;
        } else if (tid == 4) {                           // pack 8 biases -> uint4
            uint4 q;
            __half2 h0 = __floats2half2_rn(sfold[0][4], sfold[1][4]);
            __half2 h1 = __floats2half2_rn(sfold[2][4], sfold[3][4]);
            __half2 h2 = __floats2half2_rn(sfold[4][4], sfold[5][4]);
            __half2 h3 = __floats2half2_rn(sfold[6][4], sfold[7][4]);
            q.x = *reinterpret_cast<unsigned*>(&h0);
            q.y = *reinterpret_cast<unsigned*>(&h1);
            q.z = *reinterpret_cast<unsigned*>(&h2);
            q.w = *reinterpret_cast<unsigned*>(&h3);
            d_kb[b][r][part] = q;
        }

        if (bid == 0) {                                  // folded guide weights (fp32)
            if (tid >= 64 && tid < 96) {
                int rr = (tid - 64) >> 2, jj = tid & 3;
                float s = 0.f;
                for (int cc = 0; cc < 64; cc++) s += Wg[rr * 64 + cc] * W1[cc * 4 + jj];
                d_wgp[rr][jj] = s;
            } else if (tid >= 96 && tid < 104) {
                int rr = tid - 96;
                float s = bg[rr];
                for (int cc = 0; cc < 64; cc++) s += Wg[rr * 64 + cc] * b1[cc];
                d_bgp[rr] = s;
            }
        }
    }

    // ---- reset counters for next graph replay ----
    __syncthreads();
    if (tid == 0) {
        int t = atomicAdd(&d_c2, 1);
        if (t == SGRID - 1) {
            d_c1 = 0;
            __threadfence();
            d_c2 = 0;
        }
    }
}

// ---------------- 2) streaming main pass: fp32 argmax + HFMA2 matvec, pixel-pair STG.64 ----------------
// 2 px/thread, 128 thr/block, grid (256,4) = 1024 blocks (6.9 blk/SM -> ~28 warps/SM).
// launch_bounds(128,7) -> 72 regs: room to batch all 10 LDS.128 per group for MLP.
__global__ void __launch_bounds__(128, 7) main_kernel(const float* __restrict__ rgb,
                                                      const float* __restrict__ edge,
                                                      float* __restrict__ out) {
    __shared__ __align__(16) uint4 skw[R_][33];          // weight pair quads, padded stride
    __shared__ __align__(16) uint4 skb[R_][9];           // bias groups, padded stride
    __shared__ float4 sgw[R_];
    __shared__ float  sgb[R_];
    int tid = threadIdx.x;
    int b = blockIdx.y;
    int p = blockIdx.x * 256 + tid * 2;                  // 2 consecutive pixels

    // input loads first (longest latency), hidden behind smem fill
    const float* base = rgb + (size_t)b * 3 * HW;
    float2 X0 = *(const float2*)(base + p);
    float2 X1 = *(const float2*)(base + HW + p);
    float2 X2 = *(const float2*)(base + 2 * HW + p);
    float2 X3 = *(const float2*)(edge + (size_t)b * HW + p);

    {   // weights: 256 uint4 with 128 threads (2 iters)
        const uint4* src = &d_kw[b][0][0];
        int i0 = tid, i1 = tid + 128;
        skw[i0 >> 5][i0 & 31] = src[i0];
        skw[i1 >> 5][i1 & 31] = src[i1];
    }
    if (tid < 64) {                                      // bias: 8 regions x 8 uint4
        const uint4* src = &d_kb[b][0][0];
        skb[tid >> 3][tid & 7] = src[tid];
    }
    if (tid < 8) {
        sgw[tid] = *(const float4*)d_wgp[tid];
        sgb[tid] = d_bgp[tid];
    }
    __syncthreads();

    // per-pixel argmax in fp32 (strict > keeps first max, matching jnp.argmax)
    float best0 = -3.4e38f, best1 = -3.4e38f;
    int ri0 = 0, ri1 = 0;
#pragma unroll
    for (int r = 0; r < 8; r++) {
        float4 w = sgw[r];
        float gb = sgb[r];
        float gv0 = gb + w.x * X0.x + w.y * X1.x + w.z * X2.x + w.w * X3.x;
        float gv1 = gb + w.x * X0.y + w.y * X1.y + w.z * X2.y + w.w * X3.y;
        if (gv0 > best0) { best0 = gv0; ri0 = r; }
        if (gv1 > best1) { best1 = gv1; ri1 = r; }
    }

    // duplicate each pixel's inputs into half2
    __half2 h00 = __float2half2_rn(X0.x), h01 = __float2half2_rn(X1.x);
    __half2 h02 = __float2half2_rn(X2.x), h03 = __float2half2_rn(X3.x);
    __half2 h10 = __float2half2_rn(X0.y), h11 = __float2half2_rn(X1.y);
    __half2 h12 = __float2half2_rn(X2.y), h13 = __float2half2_rn(X3.y);

    const uint4* w0row = &skw[ri0][0];
    const uint4* w1row = &skw[ri1][0];
    const uint4* b0row = &skb[ri0][0];
    const uint4* b1row = &skb[ri1][0];
    float* op = out + (size_t)b * 64 * HW + p;

#pragma unroll 2
    for (int g = 0; g < 8; g++) {                        // 8 channels per group
        // batch all 10 independent LDS.128 (both pixels) up front
        uint4 bq0  = b0row[g];
        uint4 aq0 = w0row[4 * g + 0];
        uint4 aq1 = w0row[4 * g + 1];
        uint4 aq2 = w0row[4 * g + 2];
        uint4 aq3 = w0row[4 * g + 3];
        uint4 bq1  = b1row[g];
        uint4 cq0 = w1row[4 * g + 0];
        uint4 cq1 = w1row[4 * g + 1];
        uint4 cq2 = w1row[4 * g + 2];
        uint4 cq3 = w1row[4 * g + 3];

        const __half2* bh0 = reinterpret_cast<const __half2*>(&bq0);
        const __half2* bh1 = reinterpret_cast<const __half2*>(&bq1);
        const __half2* a0 = reinterpret_cast<const __half2*>(&aq0);
        const __half2* a1 = reinterpret_cast<const __half2*>(&aq1);
        const __half2* a2 = reinterpret_cast<const __half2*>(&aq2);
        const __half2* a3 = reinterpret_cast<const __half2*>(&aq3);
        const __half2* c0 = reinterpret_cast<const __half2*>(&cq0);
        const __half2* c1 = reinterpret_cast<const __half2*>(&cq1);
        const __half2* c2 = reinterpret_cast<const __half2*>(&cq2);
        const __half2* c3 = reinterpret_cast<const __half2*>(&cq3);

        // pixel 0: 4 pair accumulators
        __half2 p00 = bh0[0], p01 = bh0[1], p02 = bh0[2], p03 = bh0[3];
        p00 = __hfma2(a0[0], h00, p00); p01 = __hfma2(a1[0], h00, p01);
        p02 = __hfma2(a2[0], h00, p02); p03 = __hfma2(a3[0], h00, p03);
        p00 = __hfma2(a0[1], h01, p00); p01 = __hfma2(a1[1], h01, p01);
        p02 = __hfma2(a2[1], h01, p02); p03 = __hfma2(a3[1], h01, p03);
        p00 = __hfma2(a0[2], h02, p00); p01 = __hfma2(a1[2], h02, p01);
        p02 = __hfma2(a2[2], h02, p02); p03 = __hfma2(a3[2], h02, p03);
        p00 = __hfma2(a0[3], h03, p00); p01 = __hfma2(a1[3], h03, p01);
        p02 = __hfma2(a2[3], h03, p02); p03 = __hfma2(a3[3], h03, p03);

        // pixel 1: 4 pair accumulators
        __half2 q00 = bh1[0], q01 = bh1[1], q02 = bh1[2], q03 = bh1[3];
        q00 = __hfma2(c0[0], h10, q00); q01 = __hfma2(c1[0], h10, q01);
        q02 = __hfma2(c2[0], h10, q02); q03 = __hfma2(c3[0], h10, q03);
        q00 = __hfma2(c0[1], h11, q00); q01 = __hfma2(c1[1], h11, q01);
        q02 = __hfma2(c2[1], h11, q02); q03 = __hfma2(c3[1], h11, q03);
        q00 = __hfma2(c0[2], h12, q00); q01 = __hfma2(c1[2], h12, q01);
        q02 = __hfma2(c2[2], h12, q02); q03 = __hfma2(c3[2], h12, q03);
        q00 = __hfma2(c0[3], h13, q00); q01 = __hfma2(c1[3], h13, q01);
        q02 = __hfma2(c2[3], h13, q02); q03 = __hfma2(c3[3], h13, q03);

        // stores: channel c gets float2( y_c(px0), y_c(px1) ) -> one STG.64
        float* o = op + (size_t)(8 * g) * HW;
        *(float2*)(o)          = make_float2(__low2float(p00),  __low2float(q00));
        *(float2*)(o + HW)     = make_float2(__high2float(p00), __high2float(q00));
        *(float2*)(o + 2 * HW) = make_float2(__low2float(p01),  __low2float(q01));
        *(float2*)(o + 3 * HW) = make_float2(__high2float(p01), __high2float(q01));
        *(float2*)(o + 4 * HW) = make_float2(__low2float(p02),  __low2float(q02));
        *(float2*)(o + 5 * HW) = make_float2(__high2float(p02), __high2float(q02));
        *(float2*)(o + 6 * HW) = make_float2(__low2float(p03),  __low2float(q03));
        *(float2*)(o + 7 * HW) = make_float2(__high2float(p03), __high2float(q03));
    }
}

// ---------------- launch ----------------
extern "C" void kernel_launch(void* const* d_in, const int* in_sizes, int n_in,
                              void* d_out, int out_size) {
    const float* rgb  = (const float*)d_in[0];
    const float* edge = (const float*)d_in[1];
    const float* W1   = (const float*)d_in[2];
    const float* b1   = (const float*)d_in[3];
    const float* Wk1  = (const float*)d_in[4];
    const float* bk1  = (const float*)d_in[5];
    const float* Wk2  = (const float*)d_in[6];
    const float* bk2  = (const float*)d_in[7];
    const float* Wg   = (const float*)d_in[8];
    const float* bg   = (const float*)d_in[9];
    float* out = (float*)d_out;

    setup_fused<<<SGRID, 256>>>(rgb, edge, W1, b1, Wk1, bk1, Wk2, bk2, Wg, bg);
    main_kernel<<<dim3(256, B_), 128>>>(rgb, edge, out);
}

// round 17
// speedup vs baseline: 1.7149x; 1.0904x over previous
#include <cuda_runtime.h>
#include <cuda_fp16.h>
#include <math.h>

#define HW 65536
#define C_ 64
#define R_ 8
#define B_ 4
#define SGRID 256

// ---------------- device scratch (no allocations allowed) ----------------
__device__ __align__(128) int scnt[B_][32];              // per-batch arrival counters, 128B apart
__device__ float d_partial[16][16];                      // [plane=(b*4+i)][chunk]
__device__ __align__(16) uint4 d_kw[B_][R_][32];         // weight pair quads (half2 x4)
__device__ __align__(16) uint4 d_kb[B_][R_][8];          // per 8-ch group: 4 bias half2
__device__ __align__(16) float d_wgp[R_][4];             // Wg @ W1 (fp32: argmax exactness)
__device__ float d_bgp[R_];                              // Wg @ b1 + bg

// ---------------- 1) fused setup: reduce -> per-batch counter sync -> spread generation ----------------
// 256 blocks x 256 threads, all co-resident. Counters are reset by main_kernel (stream-ordered),
// so this kernel is deterministic across graph replays with zero extra sync cost.
__global__ void __launch_bounds__(256) setup_fused(
        const float* __restrict__ rgb, const float* __restrict__ edge,
        const float* __restrict__ W1, const float* __restrict__ b1,
        const float* __restrict__ Wk1, const float* __restrict__ bk1,
        const float* __restrict__ Wk2, const float* __restrict__ bk2,
        const float* __restrict__ Wg, const float* __restrict__ bg) {
    int tid = threadIdx.x, bid = blockIdx.x;

    // ---- phase 1: reduce. plane = bid>>4 (0..15), chunk = bid&15 (16 x 4096 floats) ----
    {
        int plane = bid >> 4, chunk = bid & 15;
        int pb = plane >> 2, i = plane & 3;
        const float* src = (i < 3) ? (rgb + (size_t)(pb * 3 + i) * HW)
                                   : (edge + (size_t)pb * HW);
        float4 v = ((const float4*)src)[chunk * 256 + tid];
        float s = (v.x + v.y) + (v.z + v.w);
#pragma unroll
        for (int off = 16; off; off >>= 1) s += __shfl_down_sync(0xFFFFFFFFu, s, off);
        __shared__ float ws[8];
        if ((tid & 31) == 0) ws[tid >> 5] = s;
        __syncthreads();
        if (tid == 0) {
            float t = ws[0];
#pragma unroll
            for (int w = 1; w < 8; w++) t += ws[w];
            d_partial[plane][chunk] = t;
            __threadfence();
            atomicAdd(&scnt[plane >> 2][0], 1);          // 64 arrivals per batch counter
        }
    }

    // ---- phase 2: block = (b = bid>>6, r = (bid>>3)&7, part = bid&7) ----
    // waits only on its own batch's counter (64 = 4 planes x 16 chunks), volatile polls
    {
        __shared__ float m4[4], g[64], tg[8];
        __shared__ float skern[512];                     // 8 channels x 64 ci
        __shared__ float sfold[8][5];                    // [c_loc][w0..w3, bias]
        int b = bid >> 6, r = (bid >> 3) & 7, part = bid & 7;

        if (tid == 0) {
            while (*(volatile int*)&scnt[b][0] < 64) __nanosleep(64);
        }
        __syncthreads();

        if (tid < 4) {
            float s = 0.f;
#pragma unroll
            for (int ch = 0; ch < 16; ch++) s += d_partial[b * 4 + tid][ch];
            m4[tid] = s * (1.0f / 65536.0f);
        }
        __syncthreads();
        if (tid < 64) {
            g[tid] = b1[tid] + W1[tid * 4 + 0] * m4[0] + W1[tid * 4 + 1] * m4[1]
                             + W1[tid * 4 + 2] * m4[2] + W1[tid * 4 + 3] * m4[3];
        }
        __syncthreads();
        if (tid < 8) {
            int row = r * 8 + tid;
            float a = bk1[row];
#pragma unroll 8
            for (int c = 0; c < 64; c++) a += Wk1[row * 64 + c] * g[c];
            tg[tid] = 1.f / (1.f + expf(-a));
        }
        __syncthreads();

        float t0 = tg[0], t1 = tg[1], t2 = tg[2], t3 = tg[3];
        float t4 = tg[4], t5 = tg[5], t6 = tg[6], t7 = tg[7];
#pragma unroll
        for (int it = 0; it < 2; it++) {
            int e = tid + it * 256;                      // 0..511
            int o = part * 512 + e;                      // global co*64+ci within (r)
            const float4* w2 = (const float4*)(Wk2 + ((size_t)r * 4096 + o) * 8);
            float4 wa = w2[0], wb = w2[1];
            skern[e] = bk2[r * 4096 + o]
                     + t0 * wa.x + t1 * wa.y + t2 * wa.z + t3 * wa.w
                     + t4 * wb.x + t5 * wb.y + t6 * wb.z + t7 * wb.w;
        }
        __syncthreads();

        if (tid < 40) {                                  // fold through W1 / b1
            int cl = tid / 5, k = tid % 5;
            float s = 0.f;
            if (k < 4) {
#pragma unroll 8
                for (int ci = 0; ci < 64; ci++) s += skern[cl * 64 + ci] * W1[ci * 4 + k];
            } else {
#pragma unroll 8
                for (int ci = 0; ci < 64; ci++) s += skern[cl * 64 + ci] * b1[ci];
            }
            sfold[cl][k] = s;
        }
        __syncthreads();

        if (tid < 4) {                                   // pack 4 weight quads (one per pair)
            int pp = tid;
            __half2 h0 = __floats2half2_rn(sfold[2 * pp][0], sfold[2 * pp + 1][0]);
            __half2 h1 = __floats2half2_rn(sfold[2 * pp][1], sfold[2 * pp + 1][1]);
            __half2 h2 = __floats2half2_rn(sfold[2 * pp][2], sfold[2 * pp + 1][2]);
            __half2 h3 = __floats2half2_rn(sfold[2 * pp][3], sfold[2 * pp + 1][3]);
            uint4 q;
            q.x = *reinterpret_cast<unsigned*>(&h0);
            q.y = *reinterpret_cast<unsigned*>(&h1);
            q.z = *reinterpret_cast<unsigned*>(&h2);
            q.w = *reinterpret_cast<unsigned*>(&h3);
            d_kw[b][r][part * 4 + pp] = q;
        } else if (tid == 4) {                           // pack 8 biases -> uint4
            uint4 q;
            __half2 h0 = __floats2half2_rn(sfold[0][4], sfold[1][4]);
            __half2 h1 = __floats2half2_rn(sfold[2][4], sfold[3][4]);
            __half2 h2 = __floats2half2_rn(sfold[4][4], sfold[5][4]);
            __half2 h3 = __floats2half2_rn(sfold[6][4], sfold[7][4]);
            q.x = *reinterpret_cast<unsigned*>(&h0);
            q.y = *reinterpret_cast<unsigned*>(&h1);
            q.z = *reinterpret_cast<unsigned*>(&h2);
            q.w = *reinterpret_cast<unsigned*>(&h3);
            d_kb[b][r][part] = q;
        }

        if (bid == 0) {                                  // folded guide weights (fp32)
            if (tid >= 64 && tid < 96) {
                int rr = (tid - 64) >> 2, jj = tid & 3;
                float s = 0.f;
                for (int cc = 0; cc < 64; cc++) s += Wg[rr * 64 + cc] * W1[cc * 4 + jj];
                d_wgp[rr][jj] = s;
            } else if (tid >= 96 && tid < 104) {
                int rr = tid - 96;
                float s = bg[rr];
                for (int cc = 0; cc < 64; cc++) s += Wg[rr * 64 + cc] * b1[cc];
                d_bgp[rr] = s;
            }
        }
    }
}

// ---------------- 2) streaming main pass: fp32 argmax + HFMA2 matvec, pixel-pair STG.64 ----------------
// 2 px/thread, 128 thr/block, grid (256,4). launch_bounds(128,5) ~= 102 regs: room for
// ~4 groups of batched LDS.128 in flight (unroll 4). Also resets setup's counters for
// the next graph replay (stream-ordered: after this replay's setup, before the next one's).
__global__ void __launch_bounds__(128, 5) main_kernel(const float* __restrict__ rgb,
                                                      const float* __restrict__ edge,
                                                      float* __restrict__ out) {
    __shared__ __align__(16) uint4 skw[R_][33];          // weight pair quads, padded stride
    __shared__ __align__(16) uint4 skb[R_][9];           // bias groups, padded stride
    __shared__ float4 sgw[R_];
    __shared__ float  sgb[R_];
    int tid = threadIdx.x;
    int b = blockIdx.y;

    if (blockIdx.x == 0 && b == 0 && tid < B_) scnt[tid][0] = 0;   // reset sync counters

    int p = blockIdx.x * 256 + tid * 2;                  // 2 consecutive pixels

    // input loads first (longest latency), hidden behind smem fill
    const float* base = rgb + (size_t)b * 3 * HW;
    float2 X0 = *(const float2*)(base + p);
    float2 X1 = *(const float2*)(base + HW + p);
    float2 X2 = *(const float2*)(base + 2 * HW + p);
    float2 X3 = *(const float2*)(edge + (size_t)b * HW + p);

    {   // weights: 256 uint4 with 128 threads (2 iters)
        const uint4* src = &d_kw[b][0][0];
        int i0 = tid, i1 = tid + 128;
        skw[i0 >> 5][i0 & 31] = src[i0];
        skw[i1 >> 5][i1 & 31] = src[i1];
    }
    if (tid < 64) {                                      // bias: 8 regions x 8 uint4
        const uint4* src = &d_kb[b][0][0];
        skb[tid >> 3][tid & 7] = src[tid];
    }
    if (tid < 8) {
        sgw[tid] = *(const float4*)d_wgp[tid];
        sgb[tid] = d_bgp[tid];
    }
    __syncthreads();

    // per-pixel argmax in fp32 (strict > keeps first max, matching jnp.argmax)
    float best0 = -3.4e38f, best1 = -3.4e38f;
    int ri0 = 0, ri1 = 0;
#pragma unroll
    for (int r = 0; r < 8; r++) {
        float4 w = sgw[r];
        float gb = sgb[r];
        float gv0 = gb + w.x * X0.x + w.y * X1.x + w.z * X2.x + w.w * X3.x;
        float gv1 = gb + w.x * X0.y + w.y * X1.y + w.z * X2.y + w.w * X3.y;
        if (gv0 > best0) { best0 = gv0; ri0 = r; }
        if (gv1 > best1) { best1 = gv1; ri1 = r; }
    }

    // duplicate each pixel's inputs into half2
    __half2 h00 = __float2half2_rn(X0.x), h01 = __float2half2_rn(X1.x);
    __half2 h02 = __float2half2_rn(X2.x), h03 = __float2half2_rn(X3.x);
    __half2 h10 = __float2half2_rn(X0.y), h11 = __float2half2_rn(X1.y);
    __half2 h12 = __float2half2_rn(X2.y), h13 = __float2half2_rn(X3.y);

    const uint4* w0row = &skw[ri0][0];
    const uint4* w1row = &skw[ri1][0];
    const uint4* b0row = &skb[ri0][0];
    const uint4* b1row = &skb[ri1][0];
    float* op = out + (size_t)b * 64 * HW + p;

#pragma unroll 4
    for (int g = 0; g < 8; g++) {                        // 8 channels per group
        // batch all 10 independent LDS.128 (both pixels) up front
        uint4 bq0  = b0row[g];
        uint4 aq0 = w0row[4 * g + 0];
        uint4 aq1 = w0row[4 * g + 1];
        uint4 aq2 = w0row[4 * g + 2];
        uint4 aq3 = w0row[4 * g + 3];
        uint4 bq1  = b1row[g];
        uint4 cq0 = w1row[4 * g + 0];
        uint4 cq1 = w1row[4 * g + 1];
        uint4 cq2 = w1row[4 * g + 2];
        uint4 cq3 = w1row[4 * g + 3];

        const __half2* bh0 = reinterpret_cast<const __half2*>(&bq0);
        const __half2* bh1 = reinterpret_cast<const __half2*>(&bq1);
        const __half2* a0 = reinterpret_cast<const __half2*>(&aq0);
        const __half2* a1 = reinterpret_cast<const __half2*>(&aq1);
        const __half2* a2 = reinterpret_cast<const __half2*>(&aq2);
        const __half2* a3 = reinterpret_cast<const __half2*>(&aq3);
        const __half2* c0 = reinterpret_cast<const __half2*>(&cq0);
        const __half2* c1 = reinterpret_cast<const __half2*>(&cq1);
        const __half2* c2 = reinterpret_cast<const __half2*>(&cq2);
        const __half2* c3 = reinterpret_cast<const __half2*>(&cq3);

        // pixel 0: 4 pair accumulators
        __half2 p00 = bh0[0], p01 = bh0[1], p02 = bh0[2], p03 = bh0[3];
        p00 = __hfma2(a0[0], h00, p00); p01 = __hfma2(a1[0], h00, p01);
        p02 = __hfma2(a2[0], h00, p02); p03 = __hfma2(a3[0], h00, p03);
        p00 = __hfma2(a0[1], h01, p00); p01 = __hfma2(a1[1], h01, p01);
        p02 = __hfma2(a2[1], h01, p02); p03 = __hfma2(a3[1], h01, p03);
        p00 = __hfma2(a0[2], h02, p00); p01 = __hfma2(a1[2], h02, p01);
        p02 = __hfma2(a2[2], h02, p02); p03 = __hfma2(a3[2], h02, p03);
        p00 = __hfma2(a0[3], h03, p00); p01 = __hfma2(a1[3], h03, p01);
        p02 = __hfma2(a2[3], h03, p02); p03 = __hfma2(a3[3], h03, p03);

        // pixel 1: 4 pair accumulators
        __half2 q00 = bh1[0], q01 = bh1[1], q02 = bh1[2], q03 = bh1[3];
        q00 = __hfma2(c0[0], h10, q00); q01 = __hfma2(c1[0], h10, q01);
        q02 = __hfma2(c2[0], h10, q02); q03 = __hfma2(c3[0], h10, q03);
        q00 = __hfma2(c0[1], h11, q00); q01 = __hfma2(c1[1], h11, q01);
        q02 = __hfma2(c2[1], h11, q02); q03 = __hfma2(c3[1], h11, q03);
        q00 = __hfma2(c0[2], h12, q00); q01 = __hfma2(c1[2], h12, q01);
        q02 = __hfma2(c2[2], h12, q02); q03 = __hfma2(c3[2], h12, q03);
        q00 = __hfma2(c0[3], h13, q00); q01 = __hfma2(c1[3], h13, q01);
        q02 = __hfma2(c2[3], h13, q02); q03 = __hfma2(c3[3], h13, q03);

        // stores: channel c gets float2( y_c(px0), y_c(px1) ) -> one STG.64
        float* o = op + (size_t)(8 * g) * HW;
        *(float2*)(o)          = make_float2(__low2float(p00),  __low2float(q00));
        *(float2*)(o + HW)     = make_float2(__high2float(p00), __high2float(q00));
        *(float2*)(o + 2 * HW) = make_float2(__low2float(p01),  __low2float(q01));
        *(float2*)(o + 3 * HW) = make_float2(__high2float(p01), __high2float(q01));
        *(float2*)(o + 4 * HW) = make_float2(__low2float(p02),  __low2float(q02));
        *(float2*)(o + 5 * HW) = make_float2(__high2float(p02), __high2float(q02));
        *(float2*)(o + 6 * HW) = make_float2(__low2float(p03),  __low2float(q03));
        *(float2*)(o + 7 * HW) = make_float2(__high2float(p03), __high2float(q03));
    }
}

// ---------------- launch ----------------
extern "C" void kernel_launch(void* const* d_in, const int* in_sizes, int n_in,
                              void* d_out, int out_size) {
    const float* rgb  = (const float*)d_in[0];
    const float* edge = (const float*)d_in[1];
    const float* W1   = (const float*)d_in[2];
    const float* b1   = (const float*)d_in[3];
    const float* Wk1  = (const float*)d_in[4];
    const float* bk1  = (const float*)d_in[5];
    const float* Wk2  = (const float*)d_in[6];
    const float* bk2  = (const float*)d_in[7];
    const float* Wg   = (const float*)d_in[8];
    const float* bg   = (const float*)d_in[9];
    float* out = (float*)d_out;

    setup_fused<<<SGRID, 256>>>(rgb, edge, W1, b1, Wk1, bk1, Wk2, bk2, Wg, bg);
    main_kernel<<<dim3(256, B_), 128>>>(rgb, edge, out);
}